// round 7
// baseline (speedup 1.0000x reference)
#include <cuda_runtime.h>
#include <cuda_bf16.h>

#define TPB 128  // 4 warps/block -> 1024 blocks (R6-proven shape)

// Single fused kernel. Each warp owns TWO rows (r, r + total_warps).
// Order per block: (1) prefetch 4 independent LDG.128 of row data into regs,
// (2) div-free cyclic-table check overlapped under those loads, (3) sum-mod
// fast path (or general group-product fallback if table isn't cyclic Z_n).
__global__ void __launch_bounds__(TPB) a5_scan_kernel(
    const float* __restrict__ scale_p,
    const int* __restrict__ ids,
    const int* __restrict__ mul,
    float* __restrict__ out,
    int n, int b_rows, int t_len, int total_warps)
{
    __shared__ int s_ok;
    int tid  = threadIdx.x;
    int lane = tid & 31;
    int warp0 = (int)((blockIdx.x * (unsigned)TPB + tid) >> 5);

    int nvec = t_len >> 2;
    bool vec_ok = ((t_len & 3) == 0);

    // ---- (1) Prefetch: 4 independent LDG.128 issued before anything else ----
    int r0 = warp0;
    int r0b = r0 + total_warps;
    bool have2_0 = (r0b < b_rows);
    bool pf = vec_ok && (r0 < b_rows) && (nvec >= 64);
    const int4* pp0 = nullptr;
    const int4* pp1 = nullptr;
    int4 a0, a1, b0, b1;
    if (pf) {
        pp0 = (const int4*)(ids + (long long)r0 * t_len);
        pp1 = (const int4*)(ids + (long long)(have2_0 ? r0b : r0) * t_len);
        a0 = __ldg(pp0 + lane);
        a1 = __ldg(pp0 + lane + 32);
        b0 = __ldg(pp1 + lane);
        b1 = __ldg(pp1 + lane + 32);
    }

    // ---- (2) Div-free cyclic check, hidden under the prefetch latency ----
    if (tid == 0) s_ok = 1;
    __syncthreads();
    {
        int total = n * n;
        int a = tid / n;               // one divide total, outside the loop
        int bc = tid - a * n;
        for (int i = tid; i < total; i += TPB) {
            int e = a + bc;
            if (e >= n) e -= n;
            if (__ldg(mul + i) != e) s_ok = 0;   // benign race: all write 0
            bc += TPB;
            while (bc >= n) { bc -= n; a++; }    // <=3 iterations for small n
        }
    }
    __syncthreads();
    bool cyclic = (s_ok != 0);

    float sc = __ldg(scale_p);
    float hi = 10.0f * sc;
    float lo = -10.0f * sc;

    for (int r = warp0; r < b_rows; r += 2 * total_warps) {
        int r2 = r + total_warps;
        bool have2 = (r2 < b_rows);

        if (cyclic && vec_ok) {
            const int4* p0;
            const int4* p1;
            int s0, s1, j;
            if (r == r0 && pf) {
                // Consume prefetched first 64 vectors' worth
                p0 = pp0; p1 = pp1;
                s0 = a0.x + a0.y + a0.z + a0.w + a1.x + a1.y + a1.z + a1.w;
                s1 = b0.x + b0.y + b0.z + b0.w + b1.x + b1.y + b1.z + b1.w;
                j = lane + 64;
            } else {
                p0 = (const int4*)(ids + (long long)r * t_len);
                p1 = (const int4*)(ids + (long long)(have2 ? r2 : r) * t_len);
                s0 = 0; s1 = 0; j = lane;
            }
            #pragma unroll 4
            for (; j < nvec; j += 32) {
                int4 a = __ldg(p0 + j);
                int4 b = __ldg(p1 + j);
                s0 += a.x + a.y + a.z + a.w;
                s1 += b.x + b.y + b.z + b.w;
            }
            #pragma unroll
            for (int d = 16; d; d >>= 1) {
                s0 += __shfl_xor_sync(0xffffffffu, s0, d);
                s1 += __shfl_xor_sync(0xffffffffu, s1, d);
            }
            int sa = s0 % n;
            int sb = s1 % n;

            float* o0 = out + (long long)r * n;
            for (int i = lane; i < n; i += 32)
                o0[i] = (i == sa) ? hi : lo;
            if (have2) {
                float* o1 = out + (long long)r2 * n;
                for (int i = lane; i < n; i += 32)
                    o1[i] = (i == sb) ? hi : lo;
            }
        } else {
            // General ordered group product fallback (per row)
            for (int k = 0; k < 2; k++) {
                int rr = (k == 0) ? r : r2;
                if (k == 1 && !have2) break;
                const int* row = ids + (long long)rr * t_len;
                int s;
                if ((t_len & 31) == 0) {
                    int chunk = t_len >> 5;
                    const int* base = row + lane * chunk;
                    int q = 0;                       // identity
                    for (int j = 0; j < chunk; j++) {
                        int x = __ldg(base + j);
                        q = __ldg(mul + x * n + q);  // q = x . q
                    }
                    #pragma unroll
                    for (int d = 1; d < 32; d <<= 1) {
                        int t = __shfl_up_sync(0xffffffffu, q, d);
                        if (lane >= d) q = __ldg(mul + q * n + t);
                    }
                    s = __shfl_sync(0xffffffffu, q, 31);
                } else {
                    int q = 0;
                    if (lane == 0)
                        for (int j = 0; j < t_len; j++)
                            q = __ldg(mul + __ldg(row + j) * n + q);
                    s = __shfl_sync(0xffffffffu, q, 0);
                }
                float* orow = out + (long long)rr * n;
                for (int i = lane; i < n; i += 32)
                    orow[i] = (i == s) ? hi : lo;
            }
        }
    }
}

extern "C" void kernel_launch(void* const* d_in, const int* in_sizes, int n_in,
                              void* d_out, int out_size) {
    const float* scale = (const float*)d_in[0];
    const int*   ids   = (const int*)d_in[1];
    const int*   mul   = (const int*)d_in[2];
    float*       out   = (float*)d_out;

    int mn = in_sizes[2];
    int n = 1;
    while (n * n < mn) n++;

    int b_rows = out_size / n;              // 8192
    int t_len  = in_sizes[1] / b_rows;      // 2048

    // 2 rows per warp -> 8 rows per 4-warp block -> 1024 blocks, one wave.
    const int warps_per_block = TPB / 32;
    int blocks = (b_rows + 2 * warps_per_block - 1) / (2 * warps_per_block);
    int total_warps = blocks * warps_per_block;

    a5_scan_kernel<<<blocks, TPB>>>(scale, ids, mul, out,
                                    n, b_rows, t_len, total_warps);
}

// round 8
// speedup vs baseline: 1.0778x; 1.0778x over previous
#include <cuda_runtime.h>
#include <cuda_bf16.h>

#define TPB 128  // 4 warps/block -> 1024 blocks, one balanced wave (R6 shape)

// 0 = unknown (initial), 1 = table is cyclic Z_n in standard form, 2 = not.
// Zero-initialized at module load; recomputed identically on every launch.
__device__ volatile int g_flag;

__global__ void __launch_bounds__(TPB) a5_scan_kernel(
    const float* __restrict__ scale_p,
    const int* __restrict__ ids,
    const int* __restrict__ mul,
    float* __restrict__ out,
    int n, int b_rows, int t_len, int total_warps)
{
    int tid  = threadIdx.x;
    int lane = tid & 31;
    int warp0 = (int)((blockIdx.x * (unsigned)TPB + tid) >> 5);

    // ---- Block 0 ONLY: verify mul[a][b] == (a+b) % n, publish verdict ----
    if (blockIdx.x == 0) {
        __shared__ int s_ok;
        if (tid == 0) s_ok = 1;
        __syncthreads();
        int total = n * n;
        int a = tid / n;
        int bc = tid - a * n;
        for (int i = tid; i < total; i += TPB) {
            int e = a + bc;
            if (e >= n) e -= n;
            if (__ldg(mul + i) != e) s_ok = 0;   // benign race: all write 0
            bc += TPB;
            while (bc >= n) { bc -= n; a++; }
        }
        __syncthreads();
        if (tid == 0) {
            __threadfence();
            g_flag = s_ok ? 1 : 2;               // release verdict
        }
    }

    float sc = __ldg(scale_p);
    float hi = 10.0f * sc;
    float lo = -10.0f * sc;

    int nvec = t_len >> 2;
    bool vec_ok = ((t_len & 3) == 0);

    for (int r = warp0; r < b_rows; r += 2 * total_warps) {
        int r2 = r + total_warps;
        bool have2 = (r2 < b_rows);

        int sa = -1, sb = -1;
        if (vec_ok) {
            // ---- Unconditional sum pass (R6-proven hot loop) ----
            const int4* p0 = (const int4*)(ids + (long long)r * t_len);
            const int4* p1 = (const int4*)(ids + (long long)(have2 ? r2 : r) * t_len);
            int s0 = 0, s1 = 0;
            #pragma unroll 4
            for (int j = lane; j < nvec; j += 32) {
                int4 a = __ldg(p0 + j);
                int4 b = __ldg(p1 + j);
                s0 += a.x + a.y + a.z + a.w;
                s1 += b.x + b.y + b.z + b.w;
            }
            #pragma unroll
            for (int d = 16; d; d >>= 1) {
                s0 += __shfl_xor_sync(0xffffffffu, s0, d);
                s1 += __shfl_xor_sync(0xffffffffu, s1, d);
            }
            sa = s0 % n;
            sb = s1 % n;
        }

        // ---- Read verdict (block 0 published it long ago; spin ~never) ----
        int f = g_flag;
        while (f == 0) { __nanosleep(64); f = g_flag; }
        __threadfence();
        bool cyclic = (f == 1);

        if (cyclic && vec_ok) {
            float* o0 = out + (long long)r * n;
            for (int i = lane; i < n; i += 32)
                o0[i] = (i == sa) ? hi : lo;
            if (have2) {
                float* o1 = out + (long long)r2 * n;
                for (int i = lane; i < n; i += 32)
                    o1[i] = (i == sb) ? hi : lo;
            }
        } else {
            // General ordered group product fallback (per row)
            for (int k = 0; k < 2; k++) {
                int rr = (k == 0) ? r : r2;
                if (k == 1 && !have2) break;
                const int* row = ids + (long long)rr * t_len;
                int s;
                if ((t_len & 31) == 0) {
                    int chunk = t_len >> 5;
                    const int* base = row + lane * chunk;
                    int q = 0;                       // identity
                    for (int j = 0; j < chunk; j++) {
                        int x = __ldg(base + j);
                        q = __ldg(mul + x * n + q);  // q = x . q
                    }
                    #pragma unroll
                    for (int d = 1; d < 32; d <<= 1) {
                        int t = __shfl_up_sync(0xffffffffu, q, d);
                        if (lane >= d) q = __ldg(mul + q * n + t);
                    }
                    s = __shfl_sync(0xffffffffu, q, 31);
                } else {
                    int q = 0;
                    if (lane == 0)
                        for (int j = 0; j < t_len; j++)
                            q = __ldg(mul + __ldg(row + j) * n + q);
                    s = __shfl_sync(0xffffffffu, q, 0);
                }
                float* orow = out + (long long)rr * n;
                for (int i = lane; i < n; i += 32)
                    orow[i] = (i == s) ? hi : lo;
            }
        }
    }
}

extern "C" void kernel_launch(void* const* d_in, const int* in_sizes, int n_in,
                              void* d_out, int out_size) {
    const float* scale = (const float*)d_in[0];
    const int*   ids   = (const int*)d_in[1];
    const int*   mul   = (const int*)d_in[2];
    float*       out   = (float*)d_out;

    int mn = in_sizes[2];
    int n = 1;
    while (n * n < mn) n++;

    int b_rows = out_size / n;              // 8192
    int t_len  = in_sizes[1] / b_rows;      // 2048

    // 2 rows per warp -> 8 rows per 4-warp block -> 1024 blocks, one wave.
    const int warps_per_block = TPB / 32;
    int blocks = (b_rows + 2 * warps_per_block - 1) / (2 * warps_per_block);
    int total_warps = blocks * warps_per_block;

    a5_scan_kernel<<<blocks, TPB>>>(scale, ids, mul, out,
                                    n, b_rows, t_len, total_warps);
}

// round 9
// speedup vs baseline: 1.5603x; 1.4477x over previous
#include <cuda_runtime.h>
#include <cuda_bf16.h>

__device__ int g_is_cyclic;   // written by check kernel; read after griddepsync

// Check node: fires PDL trigger at entry so the scan kernel can launch and
// run its sum phase concurrently. 1 block x 1024 threads, 4 loads/thread.
__global__ void __launch_bounds__(1024) check_cyclic_kernel(
    const int* __restrict__ mul, int n)
{
    cudaTriggerProgrammaticLaunchCompletion();
    __shared__ int ok;
    if (threadIdx.x == 0) ok = 1;
    __syncthreads();
    int total = n * n;
    for (int i = threadIdx.x; i < total; i += 1024) {
        int a = i / n;
        int b = i - a * n;
        int e = a + b;
        if (e >= n) e -= n;
        if (__ldg(mul + i) != e) ok = 0;   // benign race: all writers store 0
    }
    __syncthreads();
    if (threadIdx.x == 0) g_is_cyclic = ok;
}

#define TPB 128  // 4 warps/block -> 1024 blocks, one balanced wave (R6 shape)

// Scan: each warp owns TWO rows, interleaved loads (R6-proven body). Sum phase
// runs concurrently with the check kernel; one cudaGridDependencySynchronize()
// before reading the verdict (no fences, no spinning).
__global__ void __launch_bounds__(TPB) a5_scan_kernel(
    const float* __restrict__ scale_p,
    const int* __restrict__ ids,
    const int* __restrict__ mul,
    float* __restrict__ out,
    int n, int b_rows, int t_len, int total_warps)
{
    int lane  = threadIdx.x & 31;
    int warp0 = (int)((blockIdx.x * (unsigned)TPB + threadIdx.x) >> 5);

    int nvec = t_len >> 2;
    bool vec_ok = ((t_len & 3) == 0);
    bool single_pass = vec_ok && (b_rows <= 2 * total_warps);

    float sc = __ldg(scale_p);
    float hi = 10.0f * sc;
    float lo = -10.0f * sc;

    if (single_pass) {
        // ---- Overlapped path: sums first, verdict after griddepsync ----
        int r  = warp0;
        int r2 = warp0 + total_warps;
        bool have1 = (r < b_rows);
        bool have2 = (r2 < b_rows);

        int sa = 0, sb = 0;
        if (have1) {
            const int4* p0 = (const int4*)(ids + (long long)r * t_len);
            const int4* p1 = (const int4*)(ids + (long long)(have2 ? r2 : r) * t_len);
            int s0 = 0, s1 = 0;
            #pragma unroll 4
            for (int j = lane; j < nvec; j += 32) {
                int4 a = __ldg(p0 + j);
                int4 b = __ldg(p1 + j);
                s0 += a.x + a.y + a.z + a.w;
                s1 += b.x + b.y + b.z + b.w;
            }
            #pragma unroll
            for (int d = 16; d; d >>= 1) {
                s0 += __shfl_xor_sync(0xffffffffu, s0, d);
                s1 += __shfl_xor_sync(0xffffffffu, s1, d);
            }
            sa = s0 % n;
            sb = s1 % n;
        }

        cudaGridDependencySynchronize();   // check kernel done + visible
        bool cyclic = (g_is_cyclic != 0);

        if (!have1) return;
        if (cyclic) {
            float* o0 = out + (long long)r * n;
            for (int i = lane; i < n; i += 32)
                o0[i] = (i == sa) ? hi : lo;
            if (have2) {
                float* o1 = out + (long long)r2 * n;
                for (int i = lane; i < n; i += 32)
                    o1[i] = (i == sb) ? hi : lo;
            }
        } else {
            // Non-cyclic fallback: ordered group product per row
            for (int k = 0; k < 2; k++) {
                int rr = (k == 0) ? r : r2;
                if (k == 1 && !have2) break;
                const int* row = ids + (long long)rr * t_len;
                int s;
                if ((t_len & 31) == 0) {
                    int chunk = t_len >> 5;
                    const int* base = row + lane * chunk;
                    int q = 0;                       // identity
                    for (int j = 0; j < chunk; j++) {
                        int x = __ldg(base + j);
                        q = __ldg(mul + x * n + q);  // q = x . q
                    }
                    #pragma unroll
                    for (int d = 1; d < 32; d <<= 1) {
                        int t = __shfl_up_sync(0xffffffffu, q, d);
                        if (lane >= d) q = __ldg(mul + q * n + t);
                    }
                    s = __shfl_sync(0xffffffffu, q, 31);
                } else {
                    int q = 0;
                    if (lane == 0)
                        for (int j = 0; j < t_len; j++)
                            q = __ldg(mul + __ldg(row + j) * n + q);
                    s = __shfl_sync(0xffffffffu, q, 0);
                }
                float* orow = out + (long long)rr * n;
                for (int i = lane; i < n; i += 32)
                    orow[i] = (i == s) ? hi : lo;
            }
        }
    } else {
        // ---- Generic path: resolve verdict up front, then R6 loop ----
        cudaGridDependencySynchronize();
        bool cyclic = (g_is_cyclic != 0);

        for (int r = warp0; r < b_rows; r += 2 * total_warps) {
            int r2 = r + total_warps;
            bool have2 = (r2 < b_rows);

            if (cyclic && vec_ok) {
                const int4* p0 = (const int4*)(ids + (long long)r * t_len);
                const int4* p1 = (const int4*)(ids + (long long)(have2 ? r2 : r) * t_len);
                int s0 = 0, s1 = 0;
                #pragma unroll 4
                for (int j = lane; j < nvec; j += 32) {
                    int4 a = __ldg(p0 + j);
                    int4 b = __ldg(p1 + j);
                    s0 += a.x + a.y + a.z + a.w;
                    s1 += b.x + b.y + b.z + b.w;
                }
                #pragma unroll
                for (int d = 16; d; d >>= 1) {
                    s0 += __shfl_xor_sync(0xffffffffu, s0, d);
                    s1 += __shfl_xor_sync(0xffffffffu, s1, d);
                }
                int sa = s0 % n;
                int sb = s1 % n;
                float* o0 = out + (long long)r * n;
                for (int i = lane; i < n; i += 32)
                    o0[i] = (i == sa) ? hi : lo;
                if (have2) {
                    float* o1 = out + (long long)r2 * n;
                    for (int i = lane; i < n; i += 32)
                        o1[i] = (i == sb) ? hi : lo;
                }
            } else {
                for (int k = 0; k < 2; k++) {
                    int rr = (k == 0) ? r : r2;
                    if (k == 1 && !have2) break;
                    const int* row = ids + (long long)rr * t_len;
                    int s;
                    if ((t_len & 31) == 0) {
                        int chunk = t_len >> 5;
                        const int* base = row + lane * chunk;
                        int q = 0;
                        for (int j = 0; j < chunk; j++) {
                            int x = __ldg(base + j);
                            q = __ldg(mul + x * n + q);
                        }
                        #pragma unroll
                        for (int d = 1; d < 32; d <<= 1) {
                            int t = __shfl_up_sync(0xffffffffu, q, d);
                            if (lane >= d) q = __ldg(mul + q * n + t);
                        }
                        s = __shfl_sync(0xffffffffu, q, 31);
                    } else {
                        int q = 0;
                        if (lane == 0)
                            for (int j = 0; j < t_len; j++)
                                q = __ldg(mul + __ldg(row + j) * n + q);
                        s = __shfl_sync(0xffffffffu, q, 0);
                    }
                    float* orow = out + (long long)rr * n;
                    for (int i = lane; i < n; i += 32)
                        orow[i] = (i == s) ? hi : lo;
                }
            }
        }
    }
}

extern "C" void kernel_launch(void* const* d_in, const int* in_sizes, int n_in,
                              void* d_out, int out_size) {
    const float* scale = (const float*)d_in[0];
    const int*   ids   = (const int*)d_in[1];
    const int*   mul   = (const int*)d_in[2];
    float*       out   = (float*)d_out;

    int mn = in_sizes[2];
    int n = 1;
    while (n * n < mn) n++;

    int b_rows = out_size / n;              // 8192
    int t_len  = in_sizes[1] / b_rows;      // 2048

    check_cyclic_kernel<<<1, 1024>>>(mul, n);

    // 2 rows per warp -> 8 rows per 4-warp block -> 1024 blocks, one wave.
    const int warps_per_block = TPB / 32;
    int blocks = (b_rows + 2 * warps_per_block - 1) / (2 * warps_per_block);
    int total_warps = blocks * warps_per_block;

    // PDL: scan may begin while the check kernel is still running; the scan's
    // cudaGridDependencySynchronize() enforces completion + visibility.
    cudaLaunchConfig_t cfg = {};
    cfg.gridDim  = dim3((unsigned)blocks, 1, 1);
    cfg.blockDim = dim3(TPB, 1, 1);
    cfg.dynamicSmemBytes = 0;
    cfg.stream = 0;  // legacy default stream (the one the harness captures)
    cudaLaunchAttribute attr[1];
    attr[0].id = cudaLaunchAttributeProgrammaticStreamSerialization;
    attr[0].val.programmaticStreamSerializationAllowed = 1;
    cfg.attrs = attr;
    cfg.numAttrs = 1;
    cudaLaunchKernelEx(&cfg, a5_scan_kernel, scale, ids, mul, out,
                       n, b_rows, t_len, total_warps);
}

// round 11
// speedup vs baseline: 1.6534x; 1.0597x over previous
#include <cuda_runtime.h>
#include <cuda_bf16.h>

__device__ int g_is_cyclic;   // written by check kernel; read after griddepsync

// Check node: fires PDL trigger at entry so the scan kernel launches and runs
// its sum phase concurrently. 1 block x 1024 threads.
__global__ void __launch_bounds__(1024) check_cyclic_kernel(
    const int* __restrict__ mul, int n)
{
    cudaTriggerProgrammaticLaunchCompletion();
    __shared__ int ok;
    if (threadIdx.x == 0) ok = 1;
    __syncthreads();
    int total = n * n;
    for (int i = threadIdx.x; i < total; i += 1024) {
        int a = i / n;
        int b = i - a * n;
        int e = a + b;
        if (e >= n) e -= n;
        if (__ldg(mul + i) != e) ok = 0;   // benign race: all writers store 0
    }
    __syncthreads();
    if (threadIdx.x == 0) g_is_cyclic = ok;
}

#define TPB 128  // 4 warps/block -> 1024 blocks, one balanced wave

// Write one-hot row of n floats as float4 stores (requires n%4==0; row base
// out+r*n is then 16B-aligned for every r).
__device__ __forceinline__ void write_onehot_vec4(float* __restrict__ orow,
                                                  int n, int s, float hi, float lo,
                                                  int lane)
{
    int nq = n >> 2;
    for (int q = lane; q < nq; q += 32) {
        int c = q << 2;
        float4 v;
        v.x = (c + 0 == s) ? hi : lo;
        v.y = (c + 1 == s) ? hi : lo;
        v.z = (c + 2 == s) ? hi : lo;
        v.w = (c + 3 == s) ? hi : lo;
        reinterpret_cast<float4*>(orow)[q] = v;
    }
}

__device__ __forceinline__ void write_onehot_scalar(float* __restrict__ orow,
                                                    int n, int s, float hi, float lo,
                                                    int lane)
{
    for (int i = lane; i < n; i += 32)
        orow[i] = (i == s) ? hi : lo;
}

__global__ void __launch_bounds__(TPB) a5_scan_kernel(
    const float* __restrict__ scale_p,
    const int* __restrict__ ids,
    const int* __restrict__ mul,
    float* __restrict__ out,
    int n, int b_rows, int t_len, int total_warps)
{
    int lane  = threadIdx.x & 31;
    int warp0 = (int)((blockIdx.x * (unsigned)TPB + threadIdx.x) >> 5);

    int nvec = t_len >> 2;
    bool vec_ok = ((t_len & 3) == 0);
    bool n4 = ((n & 3) == 0);
    bool single_pass = vec_ok && (b_rows <= 2 * total_warps);

    float sc = __ldg(scale_p);
    float hi = 10.0f * sc;
    float lo = -10.0f * sc;

    if (single_pass) {
        // ---- Overlapped path: sums first, verdict after griddepsync ----
        int r  = warp0;
        int r2 = warp0 + total_warps;
        bool have1 = (r < b_rows);
        bool have2 = (r2 < b_rows);

        int sa = 0, sb = 0;
        if (have1) {
            const int4* p0 = (const int4*)(ids + (long long)r * t_len);
            const int4* p1 = (const int4*)(ids + (long long)(have2 ? r2 : r) * t_len);
            int s0 = 0, s1 = 0;
            #pragma unroll 4
            for (int j = lane; j < nvec; j += 32) {
                int4 a = __ldcs(p0 + j);     // streaming: read once, evict-first
                int4 b = __ldcs(p1 + j);
                s0 += a.x + a.y + a.z + a.w;
                s1 += b.x + b.y + b.z + b.w;
            }
            #pragma unroll
            for (int d = 16; d; d >>= 1) {
                s0 += __shfl_xor_sync(0xffffffffu, s0, d);
                s1 += __shfl_xor_sync(0xffffffffu, s1, d);
            }
            sa = s0 % n;
            sb = s1 % n;
        }

        cudaGridDependencySynchronize();   // check kernel done + visible
        bool cyclic = (g_is_cyclic != 0);

        if (!have1) return;
        if (cyclic) {
            float* o0 = out + (long long)r * n;
            if (n4) write_onehot_vec4(o0, n, sa, hi, lo, lane);
            else    write_onehot_scalar(o0, n, sa, hi, lo, lane);
            if (have2) {
                float* o1 = out + (long long)r2 * n;
                if (n4) write_onehot_vec4(o1, n, sb, hi, lo, lane);
                else    write_onehot_scalar(o1, n, sb, hi, lo, lane);
            }
        } else {
            // Non-cyclic fallback: ordered group product per row
            for (int k = 0; k < 2; k++) {
                int rr = (k == 0) ? r : r2;
                if (k == 1 && !have2) break;
                const int* row = ids + (long long)rr * t_len;
                int s;
                if ((t_len & 31) == 0) {
                    int chunk = t_len >> 5;
                    const int* base = row + lane * chunk;
                    int q = 0;                       // identity
                    for (int j = 0; j < chunk; j++) {
                        int x = __ldg(base + j);
                        q = __ldg(mul + x * n + q);  // q = x . q
                    }
                    #pragma unroll
                    for (int d = 1; d < 32; d <<= 1) {
                        int t = __shfl_up_sync(0xffffffffu, q, d);
                        if (lane >= d) q = __ldg(mul + q * n + t);
                    }
                    s = __shfl_sync(0xffffffffu, q, 31);
                } else {
                    int q = 0;
                    if (lane == 0)
                        for (int j = 0; j < t_len; j++)
                            q = __ldg(mul + __ldg(row + j) * n + q);
                    s = __shfl_sync(0xffffffffu, q, 0);
                }
                write_onehot_scalar(out + (long long)rr * n, n, s, hi, lo, lane);
            }
        }
    } else {
        // ---- Generic path: resolve verdict up front, then grid-stride ----
        cudaGridDependencySynchronize();
        bool cyclic = (g_is_cyclic != 0);

        for (int r = warp0; r < b_rows; r += 2 * total_warps) {
            int r2 = r + total_warps;
            bool have2 = (r2 < b_rows);

            if (cyclic && vec_ok) {
                const int4* p0 = (const int4*)(ids + (long long)r * t_len);
                const int4* p1 = (const int4*)(ids + (long long)(have2 ? r2 : r) * t_len);
                int s0 = 0, s1 = 0;
                #pragma unroll 4
                for (int j = lane; j < nvec; j += 32) {
                    int4 a = __ldcs(p0 + j);
                    int4 b = __ldcs(p1 + j);
                    s0 += a.x + a.y + a.z + a.w;
                    s1 += b.x + b.y + b.z + b.w;
                }
                #pragma unroll
                for (int d = 16; d; d >>= 1) {
                    s0 += __shfl_xor_sync(0xffffffffu, s0, d);
                    s1 += __shfl_xor_sync(0xffffffffu, s1, d);
                }
                int sa = s0 % n;
                int sb = s1 % n;
                float* o0 = out + (long long)r * n;
                if (n4) write_onehot_vec4(o0, n, sa, hi, lo, lane);
                else    write_onehot_scalar(o0, n, sa, hi, lo, lane);
                if (have2) {
                    float* o1 = out + (long long)r2 * n;
                    if (n4) write_onehot_vec4(o1, n, sb, hi, lo, lane);
                    else    write_onehot_scalar(o1, n, sb, hi, lo, lane);
                }
            } else {
                for (int k = 0; k < 2; k++) {
                    int rr = (k == 0) ? r : r2;
                    if (k == 1 && !have2) break;
                    const int* row = ids + (long long)rr * t_len;
                    int s;
                    if ((t_len & 31) == 0) {
                        int chunk = t_len >> 5;
                        const int* base = row + lane * chunk;
                        int q = 0;
                        for (int j = 0; j < chunk; j++) {
                            int x = __ldg(base + j);
                            q = __ldg(mul + x * n + q);
                        }
                        #pragma unroll
                        for (int d = 1; d < 32; d <<= 1) {
                            int t = __shfl_up_sync(0xffffffffu, q, d);
                            if (lane >= d) q = __ldg(mul + q * n + t);
                        }
                        s = __shfl_sync(0xffffffffu, q, 31);
                    } else {
                        int q = 0;
                        if (lane == 0)
                            for (int j = 0; j < t_len; j++)
                                q = __ldg(mul + __ldg(row + j) * n + q);
                        s = __shfl_sync(0xffffffffu, q, 0);
                    }
                    write_onehot_scalar(out + (long long)rr * n, n, s, hi, lo, lane);
                }
            }
        }
    }
}

extern "C" void kernel_launch(void* const* d_in, const int* in_sizes, int n_in,
                              void* d_out, int out_size) {
    const float* scale = (const float*)d_in[0];
    const int*   ids   = (const int*)d_in[1];
    const int*   mul   = (const int*)d_in[2];
    float*       out   = (float*)d_out;

    int mn = in_sizes[2];
    int n = 1;
    while (n * n < mn) n++;

    int b_rows = out_size / n;              // 8192
    int t_len  = in_sizes[1] / b_rows;      // 2048

    check_cyclic_kernel<<<1, 1024>>>(mul, n);

    // 2 rows per warp -> 8 rows per 4-warp block -> 1024 blocks, one wave.
    const int warps_per_block = TPB / 32;
    int blocks = (b_rows + 2 * warps_per_block - 1) / (2 * warps_per_block);
    int total_warps = blocks * warps_per_block;

    // PDL: scan starts while check kernel runs; griddepsync resolves verdict.
    cudaLaunchConfig_t cfg = {};
    cfg.gridDim  = dim3((unsigned)blocks, 1, 1);
    cfg.blockDim = dim3(TPB, 1, 1);
    cfg.dynamicSmemBytes = 0;
    cfg.stream = 0;
    cudaLaunchAttribute attr[1];
    attr[0].id = cudaLaunchAttributeProgrammaticStreamSerialization;
    attr[0].val.programmaticStreamSerializationAllowed = 1;
    cfg.attrs = attr;
    cfg.numAttrs = 1;
    cudaLaunchKernelEx(&cfg, a5_scan_kernel, scale, ids, mul, out,
                       n, b_rows, t_len, total_warps);
}